// round 12
// baseline (speedup 1.0000x reference)
#include <cuda_runtime.h>
#include <cuda_fp16.h>
#include <cstdint>

// Problem constants
#define BATCH 8
#define CCH   128
#define HH    256
#define WW    256
#define HWSZ  65536
#define HEADS 4
#define DIMH  32
#define WS    8
#define NWIN  32
#define EPSLN 1e-6f

// Scratch (device globals; allocation is forbidden)
__device__ float g_na[BATCH * CCH];
__device__ float g_nb[BATCH * CCH];
__device__ __half g_wf[(3 + 1) * CCH * CCH];   // qkv_w rows 0..383, proj_w rows 384..511

// ---------------------------------------------------------------------------
// Helpers (base-PTX features only: legal for compute_103)
// ---------------------------------------------------------------------------
__device__ __forceinline__ uint32_t smem_u32(const void* p) {
    uint32_t a;
    asm("{ .reg .u64 t; cvta.to.shared.u64 t, %1; cvt.u32.u64 %0, t; }" : "=r"(a) : "l"(p));
    return a;
}

#define LDSM4(r, addr) \
    asm volatile("ldmatrix.sync.aligned.m8n8.x4.shared.b16 {%0,%1,%2,%3}, [%4];" \
        : "=r"((r)[0]), "=r"((r)[1]), "=r"((r)[2]), "=r"((r)[3]) : "r"(addr))

#define LDSM4T(r, addr) \
    asm volatile("ldmatrix.sync.aligned.m8n8.x4.trans.shared.b16 {%0,%1,%2,%3}, [%4];" \
        : "=r"((r)[0]), "=r"((r)[1]), "=r"((r)[2]), "=r"((r)[3]) : "r"(addr))

#define MMAF16(d, a, b0, b1) \
    asm volatile("mma.sync.aligned.m16n8k16.row.col.f32.f16.f16.f32 " \
        "{%0,%1,%2,%3}, {%4,%5,%6,%7}, {%8,%9}, {%0,%1,%2,%3};" \
        : "+f"((d)[0]), "+f"((d)[1]), "+f"((d)[2]), "+f"((d)[3]) \
        : "r"((a)[0]), "r"((a)[1]), "r"((a)[2]), "r"((a)[3]), "r"(b0), "r"(b1))

#define CP_ASYNC16(dst, src) \
    asm volatile("cp.async.cg.shared.global [%0], [%1], 16;" :: "r"(dst), "l"(src))
#define CP_COMMIT() asm volatile("cp.async.commit_group;" ::: "memory")
#define CP_WAIT0()  asm volatile("cp.async.wait_group 0;" ::: "memory")

__device__ __forceinline__ uint32_t h2u(__half2 h) {
    uint32_t u;
    *(__half2*)&u = h;
    return u;
}

// ---------------------------------------------------------------------------
// Kernel 0: convert weights to fp16
// ---------------------------------------------------------------------------
__global__ void wconv_kernel(const float* __restrict__ qkv_w,
                             const float* __restrict__ proj_w,
                             __half* __restrict__ wf)
{
    int i = blockIdx.x * 256 + threadIdx.x;
    const int nq = 3 * CCH * CCH;
    const int nt = 4 * CCH * CCH;
    if (i < nt)
        wf[i] = __float2half_rn((i < nq) ? qkv_w[i] : proj_w[i - nq]);
}

// ---------------------------------------------------------------------------
// Kernel 1: LayerNorm2d stats -> per-(b,c) affine coefficients
// ---------------------------------------------------------------------------
__global__ void __launch_bounds__(256) ln_stats_kernel(
    const float* __restrict__ x,
    const float* __restrict__ norm_w,
    const float* __restrict__ norm_b,
    float* __restrict__ na, float* __restrict__ nb)
{
    const int bc = blockIdx.x;
    const float4* xp = (const float4*)(x + (size_t)bc * HWSZ);
    float s = 0.f, q = 0.f;
    for (int i = threadIdx.x; i < HWSZ / 4; i += 256) {
        float4 v = xp[i];
        s += v.x + v.y + v.z + v.w;
        q += v.x * v.x + v.y * v.y + v.z * v.z + v.w * v.w;
    }
    __shared__ float rs[256], rq[256];
    rs[threadIdx.x] = s; rq[threadIdx.x] = q;
    __syncthreads();
    for (int st = 128; st > 0; st >>= 1) {
        if (threadIdx.x < st) {
            rs[threadIdx.x] += rs[threadIdx.x + st];
            rq[threadIdx.x] += rq[threadIdx.x + st];
        }
        __syncthreads();
    }
    if (threadIdx.x == 0) {
        const float inv_n = 1.f / (float)HWSZ;
        float mean = rs[0] * inv_n;
        float var  = rq[0] * inv_n - mean * mean;
        int c = bc & (CCH - 1);
        float a = norm_w[c] * rsqrtf(var + EPSLN);
        na[bc] = a;
        nb[bc] = norm_b[c] - mean * a;
    }
}

// ---------------------------------------------------------------------------
// Fused kernel v4: one (b, nh, window) per CTA. 256 thr / 8 warps, 2 CTAs/SM.
// Changes vs v3: X B-frags hoisted to registers across the QKV 3-tile loop;
// ATT stored [pos][d] (STS.32, conflict-free) and proj B via non-trans LDSM.
// sX [128][72] fp16; sW [128][136]; sQKV 3x[128][72]; ATT reuses sX ([64][136]).
// ---------------------------------------------------------------------------
#define WPCH 136
#define XPCH 72
#define APCH 136
#define SX_B   0u
#define SW_B   18432u
#define SQ_B   53248u           // q; k at +18432; v at +36864
#define QT_SZ  18432u
#define FUSED_SMEM 108544u

__device__ __forceinline__ void issue_wtile(uint32_t slot, const __half* Wt, int tid) {
    #pragma unroll
    for (int rep = 0; rep < 8; rep++) {
        int s = tid + rep * 256;
        int o = s >> 4, c8 = (s & 15) * 8;
        CP_ASYNC16(slot + (uint32_t)(o * WPCH + c8) * 2u, Wt + o * CCH + c8);
    }
    CP_COMMIT();
}

__global__ void __launch_bounds__(256, 2) fused_kernel(
    const float* __restrict__ x,
    const __half* __restrict__ wf,
    const float* __restrict__ qkv_b,
    const float* __restrict__ proj_b,
    float* __restrict__ out,
    const float* __restrict__ na, const float* __restrict__ nb)
{
    extern __shared__ char smem[];
    const uint32_t sb = smem_u32(smem);
    const int tid  = threadIdx.x;
    const int wid  = tid >> 5;
    const int lane = tid & 31;
    const int wm   = wid & 3;
    const int wn   = wid >> 2;              // 0..1 -> 32-pos group
    const int nw_  = blockIdx.x;
    const int nh   = blockIdx.y;
    const int b    = blockIdx.z;
    const int sp0  = (nh * WS) * WW + nw_ * WS;

    // Prefetch W0
    issue_wtile(sb + SW_B, wf, tid);

    // --- Phase 1: X load (64 pos), LN affine, fp16 [c][t] ---
    {
        const float* Xb = x + (size_t)b * CCH * HWSZ + sp0;
        #pragma unroll
        for (int rep = 0; rep < 8; rep++) {
            int s = tid + rep * 256;
            int c = s >> 4, j4 = (s & 15) * 4;
            float4 v = *(const float4*)(Xb + (size_t)c * HWSZ + (j4 >> 3) * WW + (j4 & 7));
            float a = na[b * CCH + c], bb = nb[b * CCH + c];
            v.x = fmaf(a, v.x, bb); v.y = fmaf(a, v.y, bb);
            v.z = fmaf(a, v.z, bb); v.w = fmaf(a, v.w, bb);
            *(uint2*)(smem + SX_B + (uint32_t)(c * XPCH + j4) * 2u) = make_uint2(
                h2u(__floats2half2_rn(v.x, v.y)), h2u(__floats2half2_rn(v.z, v.w)));
        }
    }

    const uint32_t baddr = sb + SX_B +
        (uint32_t)((lane & 15) * XPCH + wn * 32 + ((lane >> 4) & 1) * 8) * 2u;
    const uint32_t aaddr = sb + SW_B +
        (uint32_t)((wm * 32 + (lane & 15)) * WPCH + (lane >> 4) * 8) * 2u;

    CP_WAIT0();
    __syncthreads();          // X staged for all; W0 landed

    // --- Hoist X B-frags into registers (invariant across the 3 W tiles) ---
    uint32_t bx[8][2][4];
    #pragma unroll
    for (int ks = 0; ks < 8; ks++) {
        LDSM4T(bx[ks][0], baddr + ks * 16 * XPCH * 2);
        LDSM4T(bx[ks][1], baddr + ks * 16 * XPCH * 2 + 32);
    }

    // --- Phase 2: QKV GEMM, 3 tiles, warp tile 32o x 32pos ---
    for (int wt = 0; wt < 3; wt++) {
        float acc[2][4][4];
        #pragma unroll
        for (int mi = 0; mi < 2; mi++)
            #pragma unroll
            for (int nf = 0; nf < 4; nf++)
                #pragma unroll
                for (int e = 0; e < 4; e++) acc[mi][nf][e] = 0.f;

        #pragma unroll
        for (int ks = 0; ks < 8; ks++) {
            uint32_t a0[4], a1[4];
            LDSM4(a0, aaddr + ks * 32);
            LDSM4(a1, aaddr + 16 * WPCH * 2 + ks * 32);
            #pragma unroll
            for (int g = 0; g < 2; g++) {
                MMAF16(acc[0][2 * g],     a0, bx[ks][g][0], bx[ks][g][1]);
                MMAF16(acc[0][2 * g + 1], a0, bx[ks][g][2], bx[ks][g][3]);
                MMAF16(acc[1][2 * g],     a1, bx[ks][g][0], bx[ks][g][1]);
                MMAF16(acc[1][2 * g + 1], a1, bx[ks][g][2], bx[ks][g][3]);
            }
        }
        __syncthreads();      // all warps done reading sW
        issue_wtile(sb + SW_B, wf + (size_t)(wt + 1) * 128 * CCH, tid);

        // Epilogue -> sQKV[wt] fp16 (+bias); overlaps cp.async stream
        const uint32_t qoff = SQ_B + (uint32_t)wt * QT_SZ;
        #pragma unroll
        for (int mi = 0; mi < 2; mi++) {
            int r = wm * 32 + mi * 16 + (lane >> 2);
            float bv0 = qkv_b[wt * 128 + r], bv1 = qkv_b[wt * 128 + r + 8];
            #pragma unroll
            for (int nf = 0; nf < 4; nf++) {
                int col = wn * 32 + nf * 8 + (lane & 3) * 2;
                *(uint32_t*)(smem + qoff + (uint32_t)(r * XPCH + col) * 2u) = h2u(
                    __floats2half2_rn(acc[mi][nf][0] + bv0, acc[mi][nf][1] + bv0));
                *(uint32_t*)(smem + qoff + (uint32_t)((r + 8) * XPCH + col) * 2u) = h2u(
                    __floats2half2_rn(acc[mi][nf][2] + bv1, acc[mi][nf][3] + bv1));
            }
        }
        if (wt < 2) {
            CP_WAIT0();
            __syncthreads();  // next W landed; epilogue visible
        }
    }
    __syncthreads();          // sQKV complete before attention reads

    // --- Phase 3: attention. warp = (hh, wq); 2 heads each ---
    {
        const int hh = wid >> 2;
        const int wq = wid & 3;
        const float scale = 0.1767766952966369f;
        const uint32_t sQt = sb + SQ_B;
        const uint32_t sKt = sQt + QT_SZ;
        const uint32_t sVt = sQt + 2 * QT_SZ;

        #pragma unroll
        for (int hi = 0; hi < 2; hi++) {
            const int hr = (hh * 2 + hi) * 32;
            const uint32_t aA = sQt +
                (uint32_t)((hr + (lane & 7) + (lane >> 4) * 8) * XPCH
                           + wq * 16 + ((lane >> 3) & 1) * 8) * 2u;
            const uint32_t bA = sKt +
                (uint32_t)((hr + (lane & 7) + ((lane >> 3) & 1) * 8) * XPCH
                           + (lane >> 4) * 8) * 2u;

            float qacc[8][4];
            #pragma unroll
            for (int nf = 0; nf < 8; nf++)
                #pragma unroll
                for (int e = 0; e < 4; e++) qacc[nf][e] = 0.f;

            #pragma unroll
            for (int ks = 0; ks < 2; ks++) {
                uint32_t a[4];
                LDSM4T(a, aA + ks * 16 * XPCH * 2);
                #pragma unroll
                for (int sg = 0; sg < 4; sg++) {
                    uint32_t bb[4];
                    LDSM4T(bb, bA + sg * 32 + ks * 16 * XPCH * 2);
                    MMAF16(qacc[2 * sg],     a, bb[0], bb[1]);
                    MMAF16(qacc[2 * sg + 1], a, bb[2], bb[3]);
                }
            }

            // Softmax (scale folded post-max)
            float mx0 = -1e30f, mx1 = -1e30f;
            #pragma unroll
            for (int nf = 0; nf < 8; nf++) {
                mx0 = fmaxf(mx0, fmaxf(qacc[nf][0], qacc[nf][1]));
                mx1 = fmaxf(mx1, fmaxf(qacc[nf][2], qacc[nf][3]));
            }
            mx0 = fmaxf(mx0, __shfl_xor_sync(0xFFFFFFFFu, mx0, 1));
            mx0 = fmaxf(mx0, __shfl_xor_sync(0xFFFFFFFFu, mx0, 2));
            mx1 = fmaxf(mx1, __shfl_xor_sync(0xFFFFFFFFu, mx1, 1));
            mx1 = fmaxf(mx1, __shfl_xor_sync(0xFFFFFFFFu, mx1, 2));

            float sm0 = 0.f, sm1 = 0.f;
            #pragma unroll
            for (int nf = 0; nf < 8; nf++) {
                qacc[nf][0] = __expf((qacc[nf][0] - mx0) * scale);
                qacc[nf][1] = __expf((qacc[nf][1] - mx0) * scale);
                qacc[nf][2] = __expf((qacc[nf][2] - mx1) * scale);
                qacc[nf][3] = __expf((qacc[nf][3] - mx1) * scale);
                sm0 += qacc[nf][0] + qacc[nf][1];
                sm1 += qacc[nf][2] + qacc[nf][3];
            }
            sm0 += __shfl_xor_sync(0xFFFFFFFFu, sm0, 1);
            sm0 += __shfl_xor_sync(0xFFFFFFFFu, sm0, 2);
            sm1 += __shfl_xor_sync(0xFFFFFFFFu, sm1, 1);
            sm1 += __shfl_xor_sync(0xFFFFFFFFu, sm1, 2);
            const float inv0 = 1.f / sm0, inv1 = 1.f / sm1;

            uint32_t pa[4][4];
            #pragma unroll
            for (int ks = 0; ks < 4; ks++) {
                int nf0 = 2 * ks, nf1 = nf0 + 1;
                pa[ks][0] = h2u(__floats2half2_rn(qacc[nf0][0] * inv0, qacc[nf0][1] * inv0));
                pa[ks][1] = h2u(__floats2half2_rn(qacc[nf0][2] * inv1, qacc[nf0][3] * inv1));
                pa[ks][2] = h2u(__floats2half2_rn(qacc[nf1][0] * inv0, qacc[nf1][1] * inv0));
                pa[ks][3] = h2u(__floats2half2_rn(qacc[nf1][2] * inv1, qacc[nf1][3] * inv1));
            }

            float oacc[4][4];
            #pragma unroll
            for (int nf = 0; nf < 4; nf++)
                #pragma unroll
                for (int e = 0; e < 4; e++) oacc[nf][e] = 0.f;

            const uint32_t vA = sVt +
                (uint32_t)((hr + (lane & 15)) * XPCH + (lane >> 4) * 8) * 2u;
            #pragma unroll
            for (int ks = 0; ks < 4; ks++) {
                #pragma unroll
                for (int ng = 0; ng < 2; ng++) {
                    uint32_t vh[4];
                    LDSM4(vh, vA + ng * 16 * XPCH * 2 + ks * 32);
                    MMAF16(oacc[2 * ng],     pa[ks], vh[0], vh[2]);
                    MMAF16(oacc[2 * ng + 1], pa[ks], vh[1], vh[3]);
                }
            }

            // Store to ATT [pos][d] (reuses sX region; X dead after phase 2).
            // Adjacent-d pair -> one STS.32; banks 4r+c -> conflict-free.
            {
                int r = lane >> 2, cb = (lane & 3) * 2;
                int col = wq * 16 + r;
                #pragma unroll
                for (int nf = 0; nf < 4; nf++) {
                    int d = hr + nf * 8 + cb;
                    *(uint32_t*)(smem + SX_B + (uint32_t)(col * APCH + d) * 2u) =
                        h2u(__floats2half2_rn(oacc[nf][0], oacc[nf][1]));
                    *(uint32_t*)(smem + SX_B + (uint32_t)((col + 8) * APCH + d) * 2u) =
                        h2u(__floats2half2_rn(oacc[nf][2], oacc[nf][3]));
                }
            }
        }
    }
    CP_WAIT0();
    __syncthreads();          // ATT complete; Wproj landed

    // --- Phase 4: proj GEMM. A = Wproj (sW); B = ATT [pos][d] non-trans LDSM ---
    {
        const uint32_t baddr2 = sb + SX_B +
            (uint32_t)((wn * 32 + (lane & 15)) * APCH + (lane >> 4) * 8) * 2u;
        float acc[2][4][4];
        #pragma unroll
        for (int mi = 0; mi < 2; mi++)
            #pragma unroll
            for (int nf = 0; nf < 4; nf++)
                #pragma unroll
                for (int e = 0; e < 4; e++) acc[mi][nf][e] = 0.f;

        #pragma unroll
        for (int ks = 0; ks < 8; ks++) {
            uint32_t a0[4], a1[4];
            LDSM4(a0, aaddr + ks * 32);
            LDSM4(a1, aaddr + 16 * WPCH * 2 + ks * 32);
            #pragma unroll
            for (int g = 0; g < 2; g++) {
                uint32_t bg[4];
                LDSM4(bg, baddr2 + g * 16 * APCH * 2 + ks * 32);
                MMAF16(acc[0][2 * g],     a0, bg[0], bg[2]);
                MMAF16(acc[0][2 * g + 1], a0, bg[1], bg[3]);
                MMAF16(acc[1][2 * g],     a1, bg[0], bg[2]);
                MMAF16(acc[1][2 * g + 1], a1, bg[1], bg[3]);
            }
        }

        // Epilogue: fp32 direct to gmem (8-float rows = full 32B sectors)
        #pragma unroll
        for (int mi = 0; mi < 2; mi++) {
            int r = wm * 32 + mi * 16 + (lane >> 2);
            float bv0 = proj_b[r], bv1 = proj_b[r + 8];
            float* O0 = out + ((size_t)b * CCH + r) * HWSZ + sp0;
            #pragma unroll
            for (int nf = 0; nf < 4; nf++) {
                int col = wn * 32 + nf * 8 + (lane & 3) * 2;
                int gpos = (col >> 3) * WW + (col & 7);
                *(float2*)(O0 + gpos) =
                    make_float2(acc[mi][nf][0] + bv0, acc[mi][nf][1] + bv0);
                *(float2*)(O0 + (size_t)8 * HWSZ + gpos) =
                    make_float2(acc[mi][nf][2] + bv1, acc[mi][nf][3] + bv1);
            }
        }
    }
}

// ---------------------------------------------------------------------------
// Launch
// ---------------------------------------------------------------------------
extern "C" void kernel_launch(void* const* d_in, const int* in_sizes, int n_in,
                              void* d_out, int out_size)
{
    const float* x      = (const float*)d_in[0];
    const float* norm_w = (const float*)d_in[1];
    const float* norm_b = (const float*)d_in[2];
    const float* qkv_w  = (const float*)d_in[3];
    const float* qkv_b  = (const float*)d_in[4];
    const float* proj_w = (const float*)d_in[5];
    const float* proj_b = (const float*)d_in[6];
    float* out = (float*)d_out;

    float *na, *nb;
    __half *wf;
    cudaGetSymbolAddress((void**)&na, g_na);
    cudaGetSymbolAddress((void**)&nb, g_nb);
    cudaGetSymbolAddress((void**)&wf, g_wf);

    cudaFuncSetAttribute(fused_kernel,
                         cudaFuncAttributeMaxDynamicSharedMemorySize, FUSED_SMEM);

    // 0) Weight convert (tiny)
    wconv_kernel<<<(4 * CCH * CCH + 255) / 256, 256>>>(qkv_w, proj_w, wf);

    // 1) LayerNorm stats
    ln_stats_kernel<<<BATCH * CCH, 256>>>(x, norm_w, norm_b, na, nb);

    // 2) Fused LN-affine + QKV + attention + proj
    fused_kernel<<<dim3(NWIN, NWIN, BATCH), 256, FUSED_SMEM>>>(
        x, wf, qkv_b, proj_b, out, na, nb);
}

// round 13
// speedup vs baseline: 1.0239x; 1.0239x over previous
#include <cuda_runtime.h>
#include <cuda_fp16.h>
#include <cstdint>

// Problem constants
#define BATCH 8
#define CCH   128
#define HH    256
#define WW    256
#define HWSZ  65536
#define HEADS 4
#define DIMH  32
#define WS    8
#define NWIN  32
#define EPSLN 1e-6f

// Scratch (device globals; allocation is forbidden)
__device__ float g_na[BATCH * CCH];
__device__ float g_nb[BATCH * CCH];
__device__ __half g_wf[(3 + 1) * CCH * CCH];   // qkv_w rows 0..383, proj_w rows 384..511

// ---------------------------------------------------------------------------
// Helpers (base-PTX features only: legal for compute_103)
// ---------------------------------------------------------------------------
__device__ __forceinline__ uint32_t smem_u32(const void* p) {
    uint32_t a;
    asm("{ .reg .u64 t; cvta.to.shared.u64 t, %1; cvt.u32.u64 %0, t; }" : "=r"(a) : "l"(p));
    return a;
}

#define LDSM4(r, addr) \
    asm volatile("ldmatrix.sync.aligned.m8n8.x4.shared.b16 {%0,%1,%2,%3}, [%4];" \
        : "=r"((r)[0]), "=r"((r)[1]), "=r"((r)[2]), "=r"((r)[3]) : "r"(addr))

#define LDSM4T(r, addr) \
    asm volatile("ldmatrix.sync.aligned.m8n8.x4.trans.shared.b16 {%0,%1,%2,%3}, [%4];" \
        : "=r"((r)[0]), "=r"((r)[1]), "=r"((r)[2]), "=r"((r)[3]) : "r"(addr))

#define MMAF16(d, a, b0, b1) \
    asm volatile("mma.sync.aligned.m16n8k16.row.col.f32.f16.f16.f32 " \
        "{%0,%1,%2,%3}, {%4,%5,%6,%7}, {%8,%9}, {%0,%1,%2,%3};" \
        : "+f"((d)[0]), "+f"((d)[1]), "+f"((d)[2]), "+f"((d)[3]) \
        : "r"((a)[0]), "r"((a)[1]), "r"((a)[2]), "r"((a)[3]), "r"(b0), "r"(b1))

#define CP_ASYNC16(dst, src) \
    asm volatile("cp.async.cg.shared.global [%0], [%1], 16;" :: "r"(dst), "l"(src))
#define CP_COMMIT() asm volatile("cp.async.commit_group;" ::: "memory")
#define CP_WAIT1()  asm volatile("cp.async.wait_group 1;" ::: "memory")
#define CP_WAIT0()  asm volatile("cp.async.wait_group 0;" ::: "memory")

__device__ __forceinline__ uint32_t h2u(__half2 h) {
    uint32_t u;
    *(__half2*)&u = h;
    return u;
}

// ---------------------------------------------------------------------------
// Kernel 0: convert weights to fp16
// ---------------------------------------------------------------------------
__global__ void wconv_kernel(const float* __restrict__ qkv_w,
                             const float* __restrict__ proj_w,
                             __half* __restrict__ wf)
{
    int i = blockIdx.x * 256 + threadIdx.x;
    const int nq = 3 * CCH * CCH;
    const int nt = 4 * CCH * CCH;
    if (i < nt)
        wf[i] = __float2half_rn((i < nq) ? qkv_w[i] : proj_w[i - nq]);
}

// ---------------------------------------------------------------------------
// Kernel 1: LayerNorm2d stats -> per-(b,c) affine coefficients
// ---------------------------------------------------------------------------
__global__ void __launch_bounds__(256) ln_stats_kernel(
    const float* __restrict__ x,
    const float* __restrict__ norm_w,
    const float* __restrict__ norm_b,
    float* __restrict__ na, float* __restrict__ nb)
{
    const int bc = blockIdx.x;
    const float4* xp = (const float4*)(x + (size_t)bc * HWSZ);
    float s = 0.f, q = 0.f;
    #pragma unroll 4
    for (int i = threadIdx.x; i < HWSZ / 4; i += 256) {
        float4 v = xp[i];
        s += v.x + v.y + v.z + v.w;
        q += v.x * v.x + v.y * v.y + v.z * v.z + v.w * v.w;
    }
    __shared__ float rs[256], rq[256];
    rs[threadIdx.x] = s; rq[threadIdx.x] = q;
    __syncthreads();
    for (int st = 128; st > 0; st >>= 1) {
        if (threadIdx.x < st) {
            rs[threadIdx.x] += rs[threadIdx.x + st];
            rq[threadIdx.x] += rq[threadIdx.x + st];
        }
        __syncthreads();
    }
    if (threadIdx.x == 0) {
        const float inv_n = 1.f / (float)HWSZ;
        float mean = rs[0] * inv_n;
        float var  = rq[0] * inv_n - mean * mean;
        int c = bc & (CCH - 1);
        float a = norm_w[c] * rsqrtf(var + EPSLN);
        na[bc] = a;
        nb[bc] = norm_b[c] - mean * a;
    }
}

// ---------------------------------------------------------------------------
// Fused kernel (R10 base): 512 threads / 16 warps, one (b, nh, window-pair).
// GEMM phases: warp grid 4x4, tile 32o x 32pos. Attention: warp = (hh, win, wq),
// 2 heads per warp. ATT buffer stored [pos][d] (conflict-free STS.32);
// proj B via non-trans ldmatrix. smem 204 KB, 1 CTA/SM.
// ---------------------------------------------------------------------------
#define TP 136
#define SX_B   0u
#define SW0_B  34816u
#define SW1_B  69632u
#define SQ_B   104448u          // q tile; k at +34816, v at +69632
#define FUSED_SMEM 208896u

__device__ __forceinline__ void issue_wtile(uint32_t slot, const __half* Wt, int tid) {
    #pragma unroll
    for (int rep = 0; rep < 4; rep++) {
        int s = tid + rep * 512;
        int o = s >> 4, c8 = (s & 15) * 8;
        CP_ASYNC16(slot + (uint32_t)(o * TP + c8) * 2u, Wt + o * CCH + c8);
    }
    CP_COMMIT();
}

__global__ void __launch_bounds__(512) fused_kernel(
    const float* __restrict__ x,
    const __half* __restrict__ wf,
    const float* __restrict__ qkv_b,
    const float* __restrict__ proj_b,
    float* __restrict__ out,
    const float* __restrict__ na, const float* __restrict__ nb)
{
    extern __shared__ char smem[];
    const uint32_t sb = smem_u32(smem);
    const int tid  = threadIdx.x;
    const int wid  = tid >> 5;
    const int lane = tid & 31;
    const int wm   = wid & 3;
    const int wn   = wid >> 2;              // 0..3 -> 32-pos group
    const int nwp  = blockIdx.x;
    const int nh   = blockIdx.y;
    const int b    = blockIdx.z;
    const int sp0  = (nh * WS) * WW + nwp * 16;

    // Prefetch W tiles 0,1
    issue_wtile(sb + SW0_B, wf, tid);
    issue_wtile(sb + SW1_B, wf + 128 * CCH, tid);

    // --- Phase 1: X load, LN affine, fp16, tile-col order ---
    {
        const float* Xb = x + (size_t)b * CCH * HWSZ + sp0;
        #pragma unroll
        for (int rep = 0; rep < 8; rep++) {
            int s = tid + rep * 512;
            int c = s >> 5, j4 = (s & 31) * 4;
            float4 v = *(const float4*)(Xb + (size_t)c * HWSZ + (j4 >> 4) * WW + (j4 & 15));
            float a = na[b * CCH + c], bb = nb[b * CCH + c];
            v.x = fmaf(a, v.x, bb); v.y = fmaf(a, v.y, bb);
            v.z = fmaf(a, v.z, bb); v.w = fmaf(a, v.w, bb);
            *(uint2*)(smem + SX_B + (uint32_t)(c * TP + j4) * 2u) = make_uint2(
                h2u(__floats2half2_rn(v.x, v.y)), h2u(__floats2half2_rn(v.z, v.w)));
        }
    }

    // Fragment base addresses
    const uint32_t baddr = sb + SX_B +
        (uint32_t)((lane & 15) * TP + wn * 32 + ((lane >> 4) & 1) * 8) * 2u;
    const uint32_t aoff =
        (uint32_t)((wm * 32 + (lane & 15)) * TP + (lane >> 4) * 8) * 2u;

    // --- Phase 2: QKV GEMM, 3 output tiles, warp tile 32o x 32pos ---
    for (int wt = 0; wt < 3; wt++) {
        CP_WAIT1();
        __syncthreads();
        const uint32_t aaddr = sb + ((wt & 1) ? SW1_B : SW0_B) + aoff;

        float acc[2][4][4];
        #pragma unroll
        for (int mi = 0; mi < 2; mi++)
            #pragma unroll
            for (int nf = 0; nf < 4; nf++)
                #pragma unroll
                for (int e = 0; e < 4; e++) acc[mi][nf][e] = 0.f;

        #pragma unroll
        for (int ks = 0; ks < 8; ks++) {
            uint32_t a0[4], a1[4];
            LDSM4(a0, aaddr + ks * 32);
            LDSM4(a1, aaddr + 16 * TP * 2 + ks * 32);
            #pragma unroll
            for (int g = 0; g < 2; g++) {
                uint32_t bg[4];
                LDSM4T(bg, baddr + ks * 16 * TP * 2 + g * 32);
                MMAF16(acc[0][2 * g],     a0, bg[0], bg[1]);
                MMAF16(acc[0][2 * g + 1], a0, bg[2], bg[3]);
                MMAF16(acc[1][2 * g],     a1, bg[0], bg[1]);
                MMAF16(acc[1][2 * g + 1], a1, bg[2], bg[3]);
            }
        }

        // Epilogue -> sQKV[wt] fp16 (+bias)
        const uint32_t qoff = SQ_B + (uint32_t)wt * 34816u;
        #pragma unroll
        for (int mi = 0; mi < 2; mi++) {
            int r = wm * 32 + mi * 16 + (lane >> 2);
            float bv0 = qkv_b[wt * 128 + r], bv1 = qkv_b[wt * 128 + r + 8];
            #pragma unroll
            for (int nf = 0; nf < 4; nf++) {
                int col = wn * 32 + nf * 8 + (lane & 3) * 2;
                *(uint32_t*)(smem + qoff + (uint32_t)(r * TP + col) * 2u) = h2u(
                    __floats2half2_rn(acc[mi][nf][0] + bv0, acc[mi][nf][1] + bv0));
                *(uint32_t*)(smem + qoff + (uint32_t)((r + 8) * TP + col) * 2u) = h2u(
                    __floats2half2_rn(acc[mi][nf][2] + bv1, acc[mi][nf][3] + bv1));
            }
        }
        __syncthreads();
        if (wt == 0) issue_wtile(sb + SW0_B, wf + 2 * 128 * CCH, tid);  // W2
        if (wt == 1) issue_wtile(sb + SW1_B, wf + 3 * 128 * CCH, tid);  // Wproj
    }

    // --- Phase 3: attention. warp = (hh, win, wq); 2 heads per warp ---
    {
        const int hh  = wid >> 3;           // head pair 0/1
        const int win = (wid >> 2) & 1;
        const int wq  = wid & 3;
        const int W8  = win * 8;
        const float scale = 0.1767766952966369f;
        const uint32_t sQt = sb + SQ_B;
        const uint32_t sKt = sQt + 34816u;
        const uint32_t sVt = sQt + 69632u;

        #pragma unroll
        for (int hi = 0; hi < 2; hi++) {
            const int hr = (hh * 2 + hi) * 32;
            const uint32_t aA = sQt +
                (uint32_t)((hr + (lane & 7) + (lane >> 4) * 8) * TP
                           + wq * 32 + ((lane >> 3) & 1) * 16 + W8) * 2u;
            const uint32_t bA = sKt +
                (uint32_t)((hr + (lane & 7) + ((lane >> 3) & 1) * 8) * TP
                           + (lane >> 4) * 16 + W8) * 2u;

            float qacc[8][4];
            #pragma unroll
            for (int nf = 0; nf < 8; nf++)
                #pragma unroll
                for (int e = 0; e < 4; e++) qacc[nf][e] = 0.f;

            #pragma unroll
            for (int ks = 0; ks < 2; ks++) {
                uint32_t a[4];
                LDSM4T(a, aA + ks * 16 * TP * 2);
                #pragma unroll
                for (int sg = 0; sg < 4; sg++) {
                    uint32_t bb[4];
                    LDSM4T(bb, bA + sg * 64 + ks * 16 * TP * 2);
                    MMAF16(qacc[2 * sg],     a, bb[0], bb[1]);
                    MMAF16(qacc[2 * sg + 1], a, bb[2], bb[3]);
                }
            }

            // Softmax (scale folded post-max)
            float mx0 = -1e30f, mx1 = -1e30f;
            #pragma unroll
            for (int nf = 0; nf < 8; nf++) {
                mx0 = fmaxf(mx0, fmaxf(qacc[nf][0], qacc[nf][1]));
                mx1 = fmaxf(mx1, fmaxf(qacc[nf][2], qacc[nf][3]));
            }
            mx0 = fmaxf(mx0, __shfl_xor_sync(0xFFFFFFFFu, mx0, 1));
            mx0 = fmaxf(mx0, __shfl_xor_sync(0xFFFFFFFFu, mx0, 2));
            mx1 = fmaxf(mx1, __shfl_xor_sync(0xFFFFFFFFu, mx1, 1));
            mx1 = fmaxf(mx1, __shfl_xor_sync(0xFFFFFFFFu, mx1, 2));

            float sm0 = 0.f, sm1 = 0.f;
            #pragma unroll
            for (int nf = 0; nf < 8; nf++) {
                qacc[nf][0] = __expf((qacc[nf][0] - mx0) * scale);
                qacc[nf][1] = __expf((qacc[nf][1] - mx0) * scale);
                qacc[nf][2] = __expf((qacc[nf][2] - mx1) * scale);
                qacc[nf][3] = __expf((qacc[nf][3] - mx1) * scale);
                sm0 += qacc[nf][0] + qacc[nf][1];
                sm1 += qacc[nf][2] + qacc[nf][3];
            }
            sm0 += __shfl_xor_sync(0xFFFFFFFFu, sm0, 1);
            sm0 += __shfl_xor_sync(0xFFFFFFFFu, sm0, 2);
            sm1 += __shfl_xor_sync(0xFFFFFFFFu, sm1, 1);
            sm1 += __shfl_xor_sync(0xFFFFFFFFu, sm1, 2);
            const float inv0 = 1.f / sm0, inv1 = 1.f / sm1;

            uint32_t pa[4][4];
            #pragma unroll
            for (int ks = 0; ks < 4; ks++) {
                int nf0 = 2 * ks, nf1 = nf0 + 1;
                pa[ks][0] = h2u(__floats2half2_rn(qacc[nf0][0] * inv0, qacc[nf0][1] * inv0));
                pa[ks][1] = h2u(__floats2half2_rn(qacc[nf0][2] * inv1, qacc[nf0][3] * inv1));
                pa[ks][2] = h2u(__floats2half2_rn(qacc[nf1][0] * inv0, qacc[nf1][1] * inv0));
                pa[ks][3] = h2u(__floats2half2_rn(qacc[nf1][2] * inv1, qacc[nf1][3] * inv1));
            }

            float oacc[4][4];
            #pragma unroll
            for (int nf = 0; nf < 4; nf++)
                #pragma unroll
                for (int e = 0; e < 4; e++) oacc[nf][e] = 0.f;

            const uint32_t vA = sVt +
                (uint32_t)((hr + (lane & 15)) * TP + (lane >> 4) * 16 + W8) * 2u;
            #pragma unroll
            for (int ks = 0; ks < 4; ks++) {
                #pragma unroll
                for (int ng = 0; ng < 2; ng++) {
                    uint32_t vh[4];
                    LDSM4(vh, vA + ng * 16 * TP * 2 + ks * 64);
                    MMAF16(oacc[2 * ng],     pa[ks], vh[0], vh[2]);
                    MMAF16(oacc[2 * ng + 1], pa[ks], vh[1], vh[3]);
                }
            }

            // Store ATT [pos][d] (reuses sX region). Adjacent-d pair -> STS.32,
            // banks 4r + (lane&3) + c: conflict-free.
            {
                int r = lane >> 2, cb = (lane & 3) * 2;
                int col = wq * 32 + W8 + r;
                #pragma unroll
                for (int nf = 0; nf < 4; nf++) {
                    int d = hr + nf * 8 + cb;
                    *(uint32_t*)(smem + SX_B + (uint32_t)(col * TP + d) * 2u) =
                        h2u(__floats2half2_rn(oacc[nf][0], oacc[nf][1]));
                    *(uint32_t*)(smem + SX_B + (uint32_t)((col + 16) * TP + d) * 2u) =
                        h2u(__floats2half2_rn(oacc[nf][2], oacc[nf][3]));
                }
            }
        }
    }
    CP_WAIT0();
    __syncthreads();   // ATT complete; Wproj landed

    // --- Phase 4: proj GEMM. A = Wproj (slot1); B = ATT [pos][d] non-trans ---
    {
        const uint32_t aaddr = sb + SW1_B + aoff;
        const uint32_t baddr2 = sb + SX_B +
            (uint32_t)((wn * 32 + (lane & 15)) * TP + (lane >> 4) * 8) * 2u;
        float acc[2][4][4];
        #pragma unroll
        for (int mi = 0; mi < 2; mi++)
            #pragma unroll
            for (int nf = 0; nf < 4; nf++)
                #pragma unroll
                for (int e = 0; e < 4; e++) acc[mi][nf][e] = 0.f;

        #pragma unroll
        for (int ks = 0; ks < 8; ks++) {
            uint32_t a0[4], a1[4];
            LDSM4(a0, aaddr + ks * 32);
            LDSM4(a1, aaddr + 16 * TP * 2 + ks * 32);
            #pragma unroll
            for (int g = 0; g < 2; g++) {
                uint32_t bg[4];
                LDSM4(bg, baddr2 + g * 16 * TP * 2 + ks * 32);
                MMAF16(acc[0][2 * g],     a0, bg[0], bg[2]);
                MMAF16(acc[0][2 * g + 1], a0, bg[1], bg[3]);
                MMAF16(acc[1][2 * g],     a1, bg[0], bg[2]);
                MMAF16(acc[1][2 * g + 1], a1, bg[1], bg[3]);
            }
        }

        // Epilogue: fp32 direct to gmem
        #pragma unroll
        for (int mi = 0; mi < 2; mi++) {
            int r = wm * 32 + mi * 16 + (lane >> 2);
            float bv0 = proj_b[r], bv1 = proj_b[r + 8];
            float* O0 = out + ((size_t)b * CCH + r) * HWSZ + sp0;
            #pragma unroll
            for (int nf = 0; nf < 4; nf++) {
                int col = wn * 32 + nf * 8 + (lane & 3) * 2;
                int gpos = (col >> 4) * WW + (col & 15);
                *(float2*)(O0 + gpos) =
                    make_float2(acc[mi][nf][0] + bv0, acc[mi][nf][1] + bv0);
                *(float2*)(O0 + (size_t)8 * HWSZ + gpos) =
                    make_float2(acc[mi][nf][2] + bv1, acc[mi][nf][3] + bv1);
            }
        }
    }
}

// ---------------------------------------------------------------------------
// Launch
// ---------------------------------------------------------------------------
extern "C" void kernel_launch(void* const* d_in, const int* in_sizes, int n_in,
                              void* d_out, int out_size)
{
    const float* x      = (const float*)d_in[0];
    const float* norm_w = (const float*)d_in[1];
    const float* norm_b = (const float*)d_in[2];
    const float* qkv_w  = (const float*)d_in[3];
    const float* qkv_b  = (const float*)d_in[4];
    const float* proj_w = (const float*)d_in[5];
    const float* proj_b = (const float*)d_in[6];
    float* out = (float*)d_out;

    float *na, *nb;
    __half *wf;
    cudaGetSymbolAddress((void**)&na, g_na);
    cudaGetSymbolAddress((void**)&nb, g_nb);
    cudaGetSymbolAddress((void**)&wf, g_wf);

    cudaFuncSetAttribute(fused_kernel,
                         cudaFuncAttributeMaxDynamicSharedMemorySize, FUSED_SMEM);

    // 0) Weight convert (tiny)
    wconv_kernel<<<(4 * CCH * CCH + 255) / 256, 256>>>(qkv_w, proj_w, wf);

    // 1) LayerNorm stats
    ln_stats_kernel<<<BATCH * CCH, 256>>>(x, norm_w, norm_b, na, nb);

    // 2) Fused LN-affine + QKV + attention + proj (512 threads)
    fused_kernel<<<dim3(NWIN / 2, NWIN, BATCH), 512, FUSED_SMEM>>>(
        x, wf, qkv_b, proj_b, out, na, nb);
}

// round 14
// speedup vs baseline: 1.1473x; 1.1205x over previous
#include <cuda_runtime.h>
#include <cuda_fp16.h>
#include <cstdint>

// Problem constants
#define BATCH 8
#define CCH   128
#define HH    256
#define WW    256
#define HWSZ  65536
#define HEADS 4
#define DIMH  32
#define WS    8
#define NWIN  32
#define NW_TOT 8192          // BATCH * NWIN * NWIN
#define EPSLN 1e-6f

// Scratch (device globals; allocation is forbidden)
__device__ float g_na[BATCH * CCH];
__device__ float g_nb[BATCH * CCH];
__device__ __half g_wf[(3 + 1) * CCH * CCH];   // qkv_w rows 0..383, proj_w rows 384..511

// ---------------------------------------------------------------------------
// Helpers (base-PTX features only: legal for compute_103)
// ---------------------------------------------------------------------------
__device__ __forceinline__ uint32_t smem_u32(const void* p) {
    uint32_t a;
    asm("{ .reg .u64 t; cvta.to.shared.u64 t, %1; cvt.u32.u64 %0, t; }" : "=r"(a) : "l"(p));
    return a;
}

#define LDSM4(r, addr) \
    asm volatile("ldmatrix.sync.aligned.m8n8.x4.shared.b16 {%0,%1,%2,%3}, [%4];" \
        : "=r"((r)[0]), "=r"((r)[1]), "=r"((r)[2]), "=r"((r)[3]) : "r"(addr))

#define LDSM4T(r, addr) \
    asm volatile("ldmatrix.sync.aligned.m8n8.x4.trans.shared.b16 {%0,%1,%2,%3}, [%4];" \
        : "=r"((r)[0]), "=r"((r)[1]), "=r"((r)[2]), "=r"((r)[3]) : "r"(addr))

#define MMAF16(d, a, b0, b1) \
    asm volatile("mma.sync.aligned.m16n8k16.row.col.f32.f16.f16.f32 " \
        "{%0,%1,%2,%3}, {%4,%5,%6,%7}, {%8,%9}, {%0,%1,%2,%3};" \
        : "+f"((d)[0]), "+f"((d)[1]), "+f"((d)[2]), "+f"((d)[3]) \
        : "r"((a)[0]), "r"((a)[1]), "r"((a)[2]), "r"((a)[3]), "r"(b0), "r"(b1))

#define CP_ASYNC16(dst, src) \
    asm volatile("cp.async.cg.shared.global [%0], [%1], 16;" :: "r"(dst), "l"(src))
#define CP_COMMIT() asm volatile("cp.async.commit_group;" ::: "memory")
#define CP_WAIT0()  asm volatile("cp.async.wait_group 0;" ::: "memory")

__device__ __forceinline__ uint32_t h2u(__half2 h) {
    uint32_t u;
    *(__half2*)&u = h;
    return u;
}

// ---------------------------------------------------------------------------
// Kernel 0: convert weights to fp16
// ---------------------------------------------------------------------------
__global__ void wconv_kernel(const float* __restrict__ qkv_w,
                             const float* __restrict__ proj_w,
                             __half* __restrict__ wf)
{
    int i = blockIdx.x * 256 + threadIdx.x;
    const int nq = 3 * CCH * CCH;
    const int nt = 4 * CCH * CCH;
    if (i < nt)
        wf[i] = __float2half_rn((i < nq) ? qkv_w[i] : proj_w[i - nq]);
}

// ---------------------------------------------------------------------------
// Kernel 1: LayerNorm2d stats -> per-(b,c) affine coefficients
// ---------------------------------------------------------------------------
__global__ void __launch_bounds__(256) ln_stats_kernel(
    const float* __restrict__ x,
    const float* __restrict__ norm_w,
    const float* __restrict__ norm_b,
    float* __restrict__ na, float* __restrict__ nb)
{
    const int bc = blockIdx.x;
    const float4* xp = (const float4*)(x + (size_t)bc * HWSZ);
    float s = 0.f, q = 0.f;
    #pragma unroll 4
    for (int i = threadIdx.x; i < HWSZ / 4; i += 256) {
        float4 v = xp[i];
        s += v.x + v.y + v.z + v.w;
        q += v.x * v.x + v.y * v.y + v.z * v.z + v.w * v.w;
    }
    __shared__ float rs[256], rq[256];
    rs[threadIdx.x] = s; rq[threadIdx.x] = q;
    __syncthreads();
    for (int st = 128; st > 0; st >>= 1) {
        if (threadIdx.x < st) {
            rs[threadIdx.x] += rs[threadIdx.x + st];
            rq[threadIdx.x] += rq[threadIdx.x + st];
        }
        __syncthreads();
    }
    if (threadIdx.x == 0) {
        const float inv_n = 1.f / (float)HWSZ;
        float mean = rs[0] * inv_n;
        float var  = rq[0] * inv_n - mean * mean;
        int c = bc & (CCH - 1);
        float a = norm_w[c] * rsqrtf(var + EPSLN);
        na[bc] = a;
        nb[bc] = norm_b[c] - mean * a;
    }
}

// ---------------------------------------------------------------------------
// Persistent fused kernel: grid = #SMs, each CTA grid-strides over windows.
// 256 thr / 8 warps, one 64-pos window per iteration.
// smem: W[4 tiles resident, pitch 136] 139264 | sX [128][72] 18432 |
//       sQKV 3x[128][72] 55296  = 212992 B (1 CTA/SM).
// X for the NEXT iteration is cp.async-prefetched (fp32, pitch 68) into the
// dead q+k region during proj; phase 1 converts stage->sX with LN fused.
// ---------------------------------------------------------------------------
#define WPCH 136
#define XPCH 72
#define APCH 136
#define SW_B   0u
#define WT_SZ  34816u
#define SX_B   139264u
#define SQ_B   157696u          // q; k at +18432; v at +36864
#define QT_SZ  18432u
#define STG_B  157696u          // fp32 X stage (34816 B, overlays q+k)
#define FUSED_SMEM 212992u

__device__ __forceinline__ void prefetch_x(uint32_t sb, const float* __restrict__ x,
                                           int widx, int tid)
{
    const int b = widx >> 10, nh = (widx >> 5) & 31, nw_ = widx & 31;
    const float* Xb = x + (size_t)b * CCH * HWSZ + (nh * WS) * WW + nw_ * WS;
    #pragma unroll
    for (int rep = 0; rep < 8; rep++) {
        int s = tid + rep * 256;
        int c = s >> 4, j4 = (s & 15) * 4;
        CP_ASYNC16(sb + STG_B + (uint32_t)(c * 68 + j4) * 4u,
                   Xb + (size_t)c * HWSZ + (j4 >> 3) * WW + (j4 & 7));
    }
    CP_COMMIT();
}

__global__ void __launch_bounds__(256) fused_kernel(
    const float* __restrict__ x,
    const __half* __restrict__ wf,
    const float* __restrict__ qkv_b,
    const float* __restrict__ proj_b,
    float* __restrict__ out,
    const float* __restrict__ na, const float* __restrict__ nb)
{
    extern __shared__ char smem[];
    const uint32_t sb = smem_u32(smem);
    const int tid  = threadIdx.x;
    const int wid  = tid >> 5;
    const int lane = tid & 31;
    const int wm   = wid & 3;
    const int wn   = wid >> 2;              // 0..1 -> 32-pos group

    // --- One-time: load all 4 W tiles (resident for the whole run) ---
    #pragma unroll
    for (int rep = 0; rep < 32; rep++) {
        int s = tid + rep * 256;
        int tile = s >> 11, o = (s >> 4) & 127, c8 = (s & 15) * 8;
        CP_ASYNC16(sb + SW_B + (uint32_t)tile * WT_SZ + (uint32_t)(o * WPCH + c8) * 2u,
                   wf + tile * (CCH * CCH) + o * CCH + c8);
    }
    CP_COMMIT();

    int widx = blockIdx.x;
    if (widx < NW_TOT) prefetch_x(sb, x, widx, tid);

    const uint32_t baddr = sb + SX_B +
        (uint32_t)((lane & 15) * XPCH + wn * 32 + ((lane >> 4) & 1) * 8) * 2u;
    const uint32_t aoff =
        (uint32_t)((wm * 32 + (lane & 15)) * WPCH + (lane >> 4) * 8) * 2u;

    for (; widx < NW_TOT; widx += gridDim.x) {
        const int b   = widx >> 10;
        const int nh  = (widx >> 5) & 31;
        const int nw_ = widx & 31;
        const int sp0 = (nh * WS) * WW + nw_ * WS;

        CP_WAIT0();
        __syncthreads();          // stage (+W on iter 0) landed; prev ATT reads done

        // --- Phase 1: stage fp32 -> LN affine -> fp16 sX [c][t] ---
        #pragma unroll
        for (int rep = 0; rep < 8; rep++) {
            int s = tid + rep * 256;
            int c = s >> 4, j4 = (s & 15) * 4;
            float4 v = *(const float4*)(smem + STG_B + (uint32_t)(c * 68 + j4) * 4u);
            float a = na[b * CCH + c], bb = nb[b * CCH + c];
            v.x = fmaf(a, v.x, bb); v.y = fmaf(a, v.y, bb);
            v.z = fmaf(a, v.z, bb); v.w = fmaf(a, v.w, bb);
            *(uint2*)(smem + SX_B + (uint32_t)(c * XPCH + j4) * 2u) = make_uint2(
                h2u(__floats2half2_rn(v.x, v.y)), h2u(__floats2half2_rn(v.z, v.w)));
        }
        __syncthreads();          // sX ready; stage reads complete

        // --- Phase 2: QKV GEMM, 3 tiles (W resident: no waits, no barriers) ---
        for (int wt = 0; wt < 3; wt++) {
            const uint32_t aaddr = sb + SW_B + (uint32_t)wt * WT_SZ + aoff;
            float acc[2][4][4];
            #pragma unroll
            for (int mi = 0; mi < 2; mi++)
                #pragma unroll
                for (int nf = 0; nf < 4; nf++)
                    #pragma unroll
                    for (int e = 0; e < 4; e++) acc[mi][nf][e] = 0.f;

            #pragma unroll
            for (int ks = 0; ks < 8; ks++) {
                uint32_t a0[4], a1[4];
                LDSM4(a0, aaddr + ks * 32);
                LDSM4(a1, aaddr + 16 * WPCH * 2 + ks * 32);
                #pragma unroll
                for (int g = 0; g < 2; g++) {
                    uint32_t bg[4];
                    LDSM4T(bg, baddr + ks * 16 * XPCH * 2 + g * 32);
                    MMAF16(acc[0][2 * g],     a0, bg[0], bg[1]);
                    MMAF16(acc[0][2 * g + 1], a0, bg[2], bg[3]);
                    MMAF16(acc[1][2 * g],     a1, bg[0], bg[1]);
                    MMAF16(acc[1][2 * g + 1], a1, bg[2], bg[3]);
                }
            }

            // Epilogue -> sQKV[wt] fp16 (+bias)
            const uint32_t qoff = SQ_B + (uint32_t)wt * QT_SZ;
            #pragma unroll
            for (int mi = 0; mi < 2; mi++) {
                int r = wm * 32 + mi * 16 + (lane >> 2);
                float bv0 = qkv_b[wt * 128 + r], bv1 = qkv_b[wt * 128 + r + 8];
                #pragma unroll
                for (int nf = 0; nf < 4; nf++) {
                    int col = wn * 32 + nf * 8 + (lane & 3) * 2;
                    *(uint32_t*)(smem + qoff + (uint32_t)(r * XPCH + col) * 2u) = h2u(
                        __floats2half2_rn(acc[mi][nf][0] + bv0, acc[mi][nf][1] + bv0));
                    *(uint32_t*)(smem + qoff + (uint32_t)((r + 8) * XPCH + col) * 2u) = h2u(
                        __floats2half2_rn(acc[mi][nf][2] + bv1, acc[mi][nf][3] + bv1));
                }
            }
        }
        __syncthreads();          // sQKV complete

        // --- Phase 3: attention. warp = (hh, wq); 2 heads each ---
        {
            const int hh = wid >> 2;
            const int wq = wid & 3;
            const float scale = 0.1767766952966369f;
            const uint32_t sQt = sb + SQ_B;
            const uint32_t sKt = sQt + QT_SZ;
            const uint32_t sVt = sQt + 2 * QT_SZ;

            #pragma unroll
            for (int hi = 0; hi < 2; hi++) {
                const int hr = (hh * 2 + hi) * 32;
                const uint32_t aA = sQt +
                    (uint32_t)((hr + (lane & 7) + (lane >> 4) * 8) * XPCH
                               + wq * 16 + ((lane >> 3) & 1) * 8) * 2u;
                const uint32_t bA = sKt +
                    (uint32_t)((hr + (lane & 7) + ((lane >> 3) & 1) * 8) * XPCH
                               + (lane >> 4) * 8) * 2u;

                float qacc[8][4];
                #pragma unroll
                for (int nf = 0; nf < 8; nf++)
                    #pragma unroll
                    for (int e = 0; e < 4; e++) qacc[nf][e] = 0.f;

                #pragma unroll
                for (int ks = 0; ks < 2; ks++) {
                    uint32_t a[4];
                    LDSM4T(a, aA + ks * 16 * XPCH * 2);
                    #pragma unroll
                    for (int sg = 0; sg < 4; sg++) {
                        uint32_t bb[4];
                        LDSM4T(bb, bA + sg * 32 + ks * 16 * XPCH * 2);
                        MMAF16(qacc[2 * sg],     a, bb[0], bb[1]);
                        MMAF16(qacc[2 * sg + 1], a, bb[2], bb[3]);
                    }
                }

                // Softmax (scale folded post-max)
                float mx0 = -1e30f, mx1 = -1e30f;
                #pragma unroll
                for (int nf = 0; nf < 8; nf++) {
                    mx0 = fmaxf(mx0, fmaxf(qacc[nf][0], qacc[nf][1]));
                    mx1 = fmaxf(mx1, fmaxf(qacc[nf][2], qacc[nf][3]));
                }
                mx0 = fmaxf(mx0, __shfl_xor_sync(0xFFFFFFFFu, mx0, 1));
                mx0 = fmaxf(mx0, __shfl_xor_sync(0xFFFFFFFFu, mx0, 2));
                mx1 = fmaxf(mx1, __shfl_xor_sync(0xFFFFFFFFu, mx1, 1));
                mx1 = fmaxf(mx1, __shfl_xor_sync(0xFFFFFFFFu, mx1, 2));

                float sm0 = 0.f, sm1 = 0.f;
                #pragma unroll
                for (int nf = 0; nf < 8; nf++) {
                    qacc[nf][0] = __expf((qacc[nf][0] - mx0) * scale);
                    qacc[nf][1] = __expf((qacc[nf][1] - mx0) * scale);
                    qacc[nf][2] = __expf((qacc[nf][2] - mx1) * scale);
                    qacc[nf][3] = __expf((qacc[nf][3] - mx1) * scale);
                    sm0 += qacc[nf][0] + qacc[nf][1];
                    sm1 += qacc[nf][2] + qacc[nf][3];
                }
                sm0 += __shfl_xor_sync(0xFFFFFFFFu, sm0, 1);
                sm0 += __shfl_xor_sync(0xFFFFFFFFu, sm0, 2);
                sm1 += __shfl_xor_sync(0xFFFFFFFFu, sm1, 1);
                sm1 += __shfl_xor_sync(0xFFFFFFFFu, sm1, 2);
                const float inv0 = 1.f / sm0, inv1 = 1.f / sm1;

                uint32_t pa[4][4];
                #pragma unroll
                for (int ks = 0; ks < 4; ks++) {
                    int nf0 = 2 * ks, nf1 = nf0 + 1;
                    pa[ks][0] = h2u(__floats2half2_rn(qacc[nf0][0] * inv0, qacc[nf0][1] * inv0));
                    pa[ks][1] = h2u(__floats2half2_rn(qacc[nf0][2] * inv1, qacc[nf0][3] * inv1));
                    pa[ks][2] = h2u(__floats2half2_rn(qacc[nf1][0] * inv0, qacc[nf1][1] * inv0));
                    pa[ks][3] = h2u(__floats2half2_rn(qacc[nf1][2] * inv1, qacc[nf1][3] * inv1));
                }

                float oacc[4][4];
                #pragma unroll
                for (int nf = 0; nf < 4; nf++)
                    #pragma unroll
                    for (int e = 0; e < 4; e++) oacc[nf][e] = 0.f;

                const uint32_t vA = sVt +
                    (uint32_t)((hr + (lane & 15)) * XPCH + (lane >> 4) * 8) * 2u;
                #pragma unroll
                for (int ks = 0; ks < 4; ks++) {
                    #pragma unroll
                    for (int ng = 0; ng < 2; ng++) {
                        uint32_t vh[4];
                        LDSM4(vh, vA + ng * 16 * XPCH * 2 + ks * 32);
                        MMAF16(oacc[2 * ng],     pa[ks], vh[0], vh[2]);
                        MMAF16(oacc[2 * ng + 1], pa[ks], vh[1], vh[3]);
                    }
                }

                // ATT [pos][d] in sX region: adjacent-d pair -> STS.32, conflict-free
                {
                    int r = lane >> 2, cb = (lane & 3) * 2;
                    int col = wq * 16 + r;
                    #pragma unroll
                    for (int nf = 0; nf < 4; nf++) {
                        int d = hr + nf * 8 + cb;
                        *(uint32_t*)(smem + SX_B + (uint32_t)(col * APCH + d) * 2u) =
                            h2u(__floats2half2_rn(oacc[nf][0], oacc[nf][1]));
                        *(uint32_t*)(smem + SX_B + (uint32_t)((col + 8) * APCH + d) * 2u) =
                            h2u(__floats2half2_rn(oacc[nf][2], oacc[nf][3]));
                    }
                }
            }
        }
        __syncthreads();          // ATT done; q/k reads complete

        // --- Prefetch next iteration's X into the dead q+k region ---
        if (widx + (int)gridDim.x < NW_TOT)
            prefetch_x(sb, x, widx + gridDim.x, tid);

        // --- Phase 4: proj. A = Wproj (tile 3); B = ATT [pos][d] non-trans ---
        {
            const uint32_t aaddr = sb + SW_B + 3u * WT_SZ + aoff;
            const uint32_t baddr2 = sb + SX_B +
                (uint32_t)((wn * 32 + (lane & 15)) * APCH + (lane >> 4) * 8) * 2u;
            float acc[2][4][4];
            #pragma unroll
            for (int mi = 0; mi < 2; mi++)
                #pragma unroll
                for (int nf = 0; nf < 4; nf++)
                    #pragma unroll
                    for (int e = 0; e < 4; e++) acc[mi][nf][e] = 0.f;

            #pragma unroll
            for (int ks = 0; ks < 8; ks++) {
                uint32_t a0[4], a1[4];
                LDSM4(a0, aaddr + ks * 32);
                LDSM4(a1, aaddr + 16 * WPCH * 2 + ks * 32);
                #pragma unroll
                for (int g = 0; g < 2; g++) {
                    uint32_t bg[4];
                    LDSM4(bg, baddr2 + g * 16 * APCH * 2 + ks * 32);
                    MMAF16(acc[0][2 * g],     a0, bg[0], bg[2]);
                    MMAF16(acc[0][2 * g + 1], a0, bg[1], bg[3]);
                    MMAF16(acc[1][2 * g],     a1, bg[0], bg[2]);
                    MMAF16(acc[1][2 * g + 1], a1, bg[1], bg[3]);
                }
            }

            // Epilogue: fp32 direct to gmem (8-float rows = full 32B sectors)
            #pragma unroll
            for (int mi = 0; mi < 2; mi++) {
                int r = wm * 32 + mi * 16 + (lane >> 2);
                float bv0 = proj_b[r], bv1 = proj_b[r + 8];
                float* O0 = out + ((size_t)b * CCH + r) * HWSZ + sp0;
                #pragma unroll
                for (int nf = 0; nf < 4; nf++) {
                    int col = wn * 32 + nf * 8 + (lane & 3) * 2;
                    int gpos = (col >> 3) * WW + (col & 7);
                    *(float2*)(O0 + gpos) =
                        make_float2(acc[mi][nf][0] + bv0, acc[mi][nf][1] + bv0);
                    *(float2*)(O0 + (size_t)8 * HWSZ + gpos) =
                        make_float2(acc[mi][nf][2] + bv1, acc[mi][nf][3] + bv1);
                }
            }
        }
    }
}

// ---------------------------------------------------------------------------
// Launch
// ---------------------------------------------------------------------------
extern "C" void kernel_launch(void* const* d_in, const int* in_sizes, int n_in,
                              void* d_out, int out_size)
{
    const float* x      = (const float*)d_in[0];
    const float* norm_w = (const float*)d_in[1];
    const float* norm_b = (const float*)d_in[2];
    const float* qkv_w  = (const float*)d_in[3];
    const float* qkv_b  = (const float*)d_in[4];
    const float* proj_w = (const float*)d_in[5];
    const float* proj_b = (const float*)d_in[6];
    float* out = (float*)d_out;

    float *na, *nb;
    __half *wf;
    cudaGetSymbolAddress((void**)&na, g_na);
    cudaGetSymbolAddress((void**)&nb, g_nb);
    cudaGetSymbolAddress((void**)&wf, g_wf);

    int nsm = 148;
    cudaDeviceGetAttribute(&nsm, cudaDevAttrMultiProcessorCount, 0);

    cudaFuncSetAttribute(fused_kernel,
                         cudaFuncAttributeMaxDynamicSharedMemorySize, FUSED_SMEM);

    // 0) Weight convert (tiny)
    wconv_kernel<<<(4 * CCH * CCH + 255) / 256, 256>>>(qkv_w, proj_w, wf);

    // 1) LayerNorm stats
    ln_stats_kernel<<<BATCH * CCH, 256>>>(x, norm_w, norm_b, na, nb);

    // 2) Persistent fused LN-affine + QKV + attention + proj
    fused_kernel<<<nsm, 256, FUSED_SMEM>>>(
        x, wf, qkv_b, proj_b, out, na, nb);
}

// round 15
// speedup vs baseline: 1.1520x; 1.0041x over previous
#include <cuda_runtime.h>
#include <cuda_fp16.h>
#include <cstdint>

// Problem constants
#define BATCH 8
#define CCH   128
#define HH    256
#define WW    256
#define HWSZ  65536
#define HEADS 4
#define DIMH  32
#define WS    8
#define NWIN  32
#define NW_TOT 8192          // BATCH * NWIN * NWIN
#define EPSLN 1e-6f

// Scratch (device globals; allocation is forbidden)
__device__ float g_na[BATCH * CCH];
__device__ float g_nb[BATCH * CCH];
__device__ __half g_wf[(3 + 1) * CCH * CCH];   // qkv_w rows 0..383, proj_w rows 384..511

// ---------------------------------------------------------------------------
// Helpers (base-PTX features only: legal for compute_103)
// ---------------------------------------------------------------------------
__device__ __forceinline__ uint32_t smem_u32(const void* p) {
    uint32_t a;
    asm("{ .reg .u64 t; cvta.to.shared.u64 t, %1; cvt.u32.u64 %0, t; }" : "=r"(a) : "l"(p));
    return a;
}

#define LDSM4(r, addr) \
    asm volatile("ldmatrix.sync.aligned.m8n8.x4.shared.b16 {%0,%1,%2,%3}, [%4];" \
        : "=r"((r)[0]), "=r"((r)[1]), "=r"((r)[2]), "=r"((r)[3]) : "r"(addr))

#define LDSM4T(r, addr) \
    asm volatile("ldmatrix.sync.aligned.m8n8.x4.trans.shared.b16 {%0,%1,%2,%3}, [%4];" \
        : "=r"((r)[0]), "=r"((r)[1]), "=r"((r)[2]), "=r"((r)[3]) : "r"(addr))

#define MMAF16(d, a, b0, b1) \
    asm volatile("mma.sync.aligned.m16n8k16.row.col.f32.f16.f16.f32 " \
        "{%0,%1,%2,%3}, {%4,%5,%6,%7}, {%8,%9}, {%0,%1,%2,%3};" \
        : "+f"((d)[0]), "+f"((d)[1]), "+f"((d)[2]), "+f"((d)[3]) \
        : "r"((a)[0]), "r"((a)[1]), "r"((a)[2]), "r"((a)[3]), "r"(b0), "r"(b1))

#define CP_ASYNC16(dst, src) \
    asm volatile("cp.async.cg.shared.global [%0], [%1], 16;" :: "r"(dst), "l"(src))
#define CP_COMMIT() asm volatile("cp.async.commit_group;" ::: "memory")
#define CP_WAIT0()  asm volatile("cp.async.wait_group 0;" ::: "memory")

__device__ __forceinline__ uint32_t h2u(__half2 h) {
    uint32_t u;
    *(__half2*)&u = h;
    return u;
}

// ---------------------------------------------------------------------------
// Kernel 0: convert weights to fp16
// ---------------------------------------------------------------------------
__global__ void wconv_kernel(const float* __restrict__ qkv_w,
                             const float* __restrict__ proj_w,
                             __half* __restrict__ wf)
{
    int i = blockIdx.x * 256 + threadIdx.x;
    const int nq = 3 * CCH * CCH;
    const int nt = 4 * CCH * CCH;
    if (i < nt)
        wf[i] = __float2half_rn((i < nq) ? qkv_w[i] : proj_w[i - nq]);
}

// ---------------------------------------------------------------------------
// Kernel 1: LayerNorm2d stats -> per-(b,c) affine coefficients
// ---------------------------------------------------------------------------
__global__ void __launch_bounds__(256) ln_stats_kernel(
    const float* __restrict__ x,
    const float* __restrict__ norm_w,
    const float* __restrict__ norm_b,
    float* __restrict__ na, float* __restrict__ nb)
{
    const int bc = blockIdx.x;
    const float4* xp = (const float4*)(x + (size_t)bc * HWSZ);
    float s = 0.f, q = 0.f;
    #pragma unroll 4
    for (int i = threadIdx.x; i < HWSZ / 4; i += 256) {
        float4 v = xp[i];
        s += v.x + v.y + v.z + v.w;
        q += v.x * v.x + v.y * v.y + v.z * v.z + v.w * v.w;
    }
    __shared__ float rs[256], rq[256];
    rs[threadIdx.x] = s; rq[threadIdx.x] = q;
    __syncthreads();
    for (int st = 128; st > 0; st >>= 1) {
        if (threadIdx.x < st) {
            rs[threadIdx.x] += rs[threadIdx.x + st];
            rq[threadIdx.x] += rq[threadIdx.x + st];
        }
        __syncthreads();
    }
    if (threadIdx.x == 0) {
        const float inv_n = 1.f / (float)HWSZ;
        float mean = rs[0] * inv_n;
        float var  = rq[0] * inv_n - mean * mean;
        int c = bc & (CCH - 1);
        float a = norm_w[c] * rsqrtf(var + EPSLN);
        na[bc] = a;
        nb[bc] = norm_b[c] - mean * a;
    }
}

// ---------------------------------------------------------------------------
// Persistent fused kernel: grid = #SMs, each CTA grid-strides over windows.
// 256 thr / 8 warps, one 64-pos window per iteration.
// smem: W[4 tiles resident] 139264 | sX 18432 | sQKV 3x18432 = 212992 (1 CTA/SM).
// X B-frags hoisted into registers across the 3 QKV tiles (255-reg budget).
// Next iteration's X cp.async-prefetched into dead q+k region during proj.
// ---------------------------------------------------------------------------
#define WPCH 136
#define XPCH 72
#define APCH 136
#define SW_B   0u
#define WT_SZ  34816u
#define SX_B   139264u
#define SQ_B   157696u          // q; k at +18432; v at +36864
#define QT_SZ  18432u
#define STG_B  157696u          // fp32 X stage (34816 B, overlays q+k)
#define FUSED_SMEM 212992u

__device__ __forceinline__ void prefetch_x(uint32_t sb, const float* __restrict__ x,
                                           int widx, int tid)
{
    const int b = widx >> 10, nh = (widx >> 5) & 31, nw_ = widx & 31;
    const float* Xb = x + (size_t)b * CCH * HWSZ + (nh * WS) * WW + nw_ * WS;
    #pragma unroll
    for (int rep = 0; rep < 8; rep++) {
        int s = tid + rep * 256;
        int c = s >> 4, j4 = (s & 15) * 4;
        CP_ASYNC16(sb + STG_B + (uint32_t)(c * 68 + j4) * 4u,
                   Xb + (size_t)c * HWSZ + (j4 >> 3) * WW + (j4 & 7));
    }
    CP_COMMIT();
}

__global__ void __launch_bounds__(256) fused_kernel(
    const float* __restrict__ x,
    const __half* __restrict__ wf,
    const float* __restrict__ qkv_b,
    const float* __restrict__ proj_b,
    float* __restrict__ out,
    const float* __restrict__ na, const float* __restrict__ nb)
{
    extern __shared__ char smem[];
    const uint32_t sb = smem_u32(smem);
    const int tid  = threadIdx.x;
    const int wid  = tid >> 5;
    const int lane = tid & 31;
    const int wm   = wid & 3;
    const int wn   = wid >> 2;              // 0..1 -> 32-pos group

    // --- One-time: load all 4 W tiles (resident for the whole run) ---
    #pragma unroll
    for (int rep = 0; rep < 32; rep++) {
        int s = tid + rep * 256;
        int tile = s >> 11, o = (s >> 4) & 127, c8 = (s & 15) * 8;
        CP_ASYNC16(sb + SW_B + (uint32_t)tile * WT_SZ + (uint32_t)(o * WPCH + c8) * 2u,
                   wf + tile * (CCH * CCH) + o * CCH + c8);
    }
    CP_COMMIT();

    int widx = blockIdx.x;
    if (widx < NW_TOT) prefetch_x(sb, x, widx, tid);

    const uint32_t baddr = sb + SX_B +
        (uint32_t)((lane & 15) * XPCH + wn * 32 + ((lane >> 4) & 1) * 8) * 2u;
    const uint32_t aoff =
        (uint32_t)((wm * 32 + (lane & 15)) * WPCH + (lane >> 4) * 8) * 2u;

    for (; widx < NW_TOT; widx += gridDim.x) {
        const int b   = widx >> 10;
        const int nh  = (widx >> 5) & 31;
        const int nw_ = widx & 31;
        const int sp0 = (nh * WS) * WW + nw_ * WS;

        CP_WAIT0();
        __syncthreads();          // stage (+W on iter 0) landed; prev ATT reads done

        // --- Phase 1: stage fp32 -> LN affine -> fp16 sX [c][t] ---
        #pragma unroll
        for (int rep = 0; rep < 8; rep++) {
            int s = tid + rep * 256;
            int c = s >> 4, j4 = (s & 15) * 4;
            float4 v = *(const float4*)(smem + STG_B + (uint32_t)(c * 68 + j4) * 4u);
            float a = na[b * CCH + c], bb = nb[b * CCH + c];
            v.x = fmaf(a, v.x, bb); v.y = fmaf(a, v.y, bb);
            v.z = fmaf(a, v.z, bb); v.w = fmaf(a, v.w, bb);
            *(uint2*)(smem + SX_B + (uint32_t)(c * XPCH + j4) * 2u) = make_uint2(
                h2u(__floats2half2_rn(v.x, v.y)), h2u(__floats2half2_rn(v.z, v.w)));
        }
        __syncthreads();          // sX ready; stage reads complete

        // --- Hoist X B-frags into registers (invariant over the 3 W tiles) ---
        uint32_t bx[8][2][4];
        #pragma unroll
        for (int ks = 0; ks < 8; ks++) {
            LDSM4T(bx[ks][0], baddr + ks * 16 * XPCH * 2);
            LDSM4T(bx[ks][1], baddr + ks * 16 * XPCH * 2 + 32);
        }

        // --- Phase 2: QKV GEMM, 3 tiles (W resident; X in registers) ---
        for (int wt = 0; wt < 3; wt++) {
            const uint32_t aaddr = sb + SW_B + (uint32_t)wt * WT_SZ + aoff;
            float acc[2][4][4];
            #pragma unroll
            for (int mi = 0; mi < 2; mi++)
                #pragma unroll
                for (int nf = 0; nf < 4; nf++)
                    #pragma unroll
                    for (int e = 0; e < 4; e++) acc[mi][nf][e] = 0.f;

            #pragma unroll
            for (int ks = 0; ks < 8; ks++) {
                uint32_t a0[4], a1[4];
                LDSM4(a0, aaddr + ks * 32);
                LDSM4(a1, aaddr + 16 * WPCH * 2 + ks * 32);
                #pragma unroll
                for (int g = 0; g < 2; g++) {
                    MMAF16(acc[0][2 * g],     a0, bx[ks][g][0], bx[ks][g][1]);
                    MMAF16(acc[0][2 * g + 1], a0, bx[ks][g][2], bx[ks][g][3]);
                    MMAF16(acc[1][2 * g],     a1, bx[ks][g][0], bx[ks][g][1]);
                    MMAF16(acc[1][2 * g + 1], a1, bx[ks][g][2], bx[ks][g][3]);
                }
            }

            // Epilogue -> sQKV[wt] fp16 (+bias)
            const uint32_t qoff = SQ_B + (uint32_t)wt * QT_SZ;
            #pragma unroll
            for (int mi = 0; mi < 2; mi++) {
                int r = wm * 32 + mi * 16 + (lane >> 2);
                float bv0 = qkv_b[wt * 128 + r], bv1 = qkv_b[wt * 128 + r + 8];
                #pragma unroll
                for (int nf = 0; nf < 4; nf++) {
                    int col = wn * 32 + nf * 8 + (lane & 3) * 2;
                    *(uint32_t*)(smem + qoff + (uint32_t)(r * XPCH + col) * 2u) = h2u(
                        __floats2half2_rn(acc[mi][nf][0] + bv0, acc[mi][nf][1] + bv0));
                    *(uint32_t*)(smem + qoff + (uint32_t)((r + 8) * XPCH + col) * 2u) = h2u(
                        __floats2half2_rn(acc[mi][nf][2] + bv1, acc[mi][nf][3] + bv1));
                }
            }
        }
        __syncthreads();          // sQKV complete

        // --- Phase 3: attention. warp = (hh, wq); 2 heads each ---
        {
            const int hh = wid >> 2;
            const int wq = wid & 3;
            const float scale = 0.1767766952966369f;
            const uint32_t sQt = sb + SQ_B;
            const uint32_t sKt = sQt + QT_SZ;
            const uint32_t sVt = sQt + 2 * QT_SZ;

            #pragma unroll
            for (int hi = 0; hi < 2; hi++) {
                const int hr = (hh * 2 + hi) * 32;
                const uint32_t aA = sQt +
                    (uint32_t)((hr + (lane & 7) + (lane >> 4) * 8) * XPCH
                               + wq * 16 + ((lane >> 3) & 1) * 8) * 2u;
                const uint32_t bA = sKt +
                    (uint32_t)((hr + (lane & 7) + ((lane >> 3) & 1) * 8) * XPCH
                               + (lane >> 4) * 8) * 2u;

                float qacc[8][4];
                #pragma unroll
                for (int nf = 0; nf < 8; nf++)
                    #pragma unroll
                    for (int e = 0; e < 4; e++) qacc[nf][e] = 0.f;

                #pragma unroll
                for (int ks = 0; ks < 2; ks++) {
                    uint32_t a[4];
                    LDSM4T(a, aA + ks * 16 * XPCH * 2);
                    #pragma unroll
                    for (int sg = 0; sg < 4; sg++) {
                        uint32_t bb[4];
                        LDSM4T(bb, bA + sg * 32 + ks * 16 * XPCH * 2);
                        MMAF16(qacc[2 * sg],     a, bb[0], bb[1]);
                        MMAF16(qacc[2 * sg + 1], a, bb[2], bb[3]);
                    }
                }

                // Softmax (scale folded post-max)
                float mx0 = -1e30f, mx1 = -1e30f;
                #pragma unroll
                for (int nf = 0; nf < 8; nf++) {
                    mx0 = fmaxf(mx0, fmaxf(qacc[nf][0], qacc[nf][1]));
                    mx1 = fmaxf(mx1, fmaxf(qacc[nf][2], qacc[nf][3]));
                }
                mx0 = fmaxf(mx0, __shfl_xor_sync(0xFFFFFFFFu, mx0, 1));
                mx0 = fmaxf(mx0, __shfl_xor_sync(0xFFFFFFFFu, mx0, 2));
                mx1 = fmaxf(mx1, __shfl_xor_sync(0xFFFFFFFFu, mx1, 1));
                mx1 = fmaxf(mx1, __shfl_xor_sync(0xFFFFFFFFu, mx1, 2));

                float sm0 = 0.f, sm1 = 0.f;
                #pragma unroll
                for (int nf = 0; nf < 8; nf++) {
                    qacc[nf][0] = __expf((qacc[nf][0] - mx0) * scale);
                    qacc[nf][1] = __expf((qacc[nf][1] - mx0) * scale);
                    qacc[nf][2] = __expf((qacc[nf][2] - mx1) * scale);
                    qacc[nf][3] = __expf((qacc[nf][3] - mx1) * scale);
                    sm0 += qacc[nf][0] + qacc[nf][1];
                    sm1 += qacc[nf][2] + qacc[nf][3];
                }
                sm0 += __shfl_xor_sync(0xFFFFFFFFu, sm0, 1);
                sm0 += __shfl_xor_sync(0xFFFFFFFFu, sm0, 2);
                sm1 += __shfl_xor_sync(0xFFFFFFFFu, sm1, 1);
                sm1 += __shfl_xor_sync(0xFFFFFFFFu, sm1, 2);
                const float inv0 = 1.f / sm0, inv1 = 1.f / sm1;

                uint32_t pa[4][4];
                #pragma unroll
                for (int ks = 0; ks < 4; ks++) {
                    int nf0 = 2 * ks, nf1 = nf0 + 1;
                    pa[ks][0] = h2u(__floats2half2_rn(qacc[nf0][0] * inv0, qacc[nf0][1] * inv0));
                    pa[ks][1] = h2u(__floats2half2_rn(qacc[nf0][2] * inv1, qacc[nf0][3] * inv1));
                    pa[ks][2] = h2u(__floats2half2_rn(qacc[nf1][0] * inv0, qacc[nf1][1] * inv0));
                    pa[ks][3] = h2u(__floats2half2_rn(qacc[nf1][2] * inv1, qacc[nf1][3] * inv1));
                }

                float oacc[4][4];
                #pragma unroll
                for (int nf = 0; nf < 4; nf++)
                    #pragma unroll
                    for (int e = 0; e < 4; e++) oacc[nf][e] = 0.f;

                const uint32_t vA = sVt +
                    (uint32_t)((hr + (lane & 15)) * XPCH + (lane >> 4) * 8) * 2u;
                #pragma unroll
                for (int ks = 0; ks < 4; ks++) {
                    #pragma unroll
                    for (int ng = 0; ng < 2; ng++) {
                        uint32_t vh[4];
                        LDSM4(vh, vA + ng * 16 * XPCH * 2 + ks * 32);
                        MMAF16(oacc[2 * ng],     pa[ks], vh[0], vh[2]);
                        MMAF16(oacc[2 * ng + 1], pa[ks], vh[1], vh[3]);
                    }
                }

                // ATT [pos][d] in sX region: adjacent-d pair -> STS.32, conflict-free
                {
                    int r = lane >> 2, cb = (lane & 3) * 2;
                    int col = wq * 16 + r;
                    #pragma unroll
                    for (int nf = 0; nf < 4; nf++) {
                        int d = hr + nf * 8 + cb;
                        *(uint32_t*)(smem + SX_B + (uint32_t)(col * APCH + d) * 2u) =
                            h2u(__floats2half2_rn(oacc[nf][0], oacc[nf][1]));
                        *(uint32_t*)(smem + SX_B + (uint32_t)((col + 8) * APCH + d) * 2u) =
                            h2u(__floats2half2_rn(oacc[nf][2], oacc[nf][3]));
                    }
                }
            }
        }
        __syncthreads();          // ATT done; q/k reads complete

        // --- Prefetch next iteration's X into the dead q+k region ---
        if (widx + (int)gridDim.x < NW_TOT)
            prefetch_x(sb, x, widx + gridDim.x, tid);

        // --- Phase 4: proj. A = Wproj (tile 3); B = ATT [pos][d] non-trans ---
        {
            const uint32_t aaddr = sb + SW_B + 3u * WT_SZ + aoff;
            const uint32_t baddr2 = sb + SX_B +
                (uint32_t)((wn * 32 + (lane & 15)) * APCH + (lane >> 4) * 8) * 2u;
            float acc[2][4][4];
            #pragma unroll
            for (int mi = 0; mi < 2; mi++)
                #pragma unroll
                for (int nf = 0; nf < 4; nf++)
                    #pragma unroll
                    for (int e = 0; e < 4; e++) acc[mi][nf][e] = 0.f;

            #pragma unroll
            for (int ks = 0; ks < 8; ks++) {
                uint32_t a0[4], a1[4];
                LDSM4(a0, aaddr + ks * 32);
                LDSM4(a1, aaddr + 16 * WPCH * 2 + ks * 32);
                #pragma unroll
                for (int g = 0; g < 2; g++) {
                    uint32_t bg[4];
                    LDSM4(bg, baddr2 + g * 16 * APCH * 2 + ks * 32);
                    MMAF16(acc[0][2 * g],     a0, bg[0], bg[2]);
                    MMAF16(acc[0][2 * g + 1], a0, bg[1], bg[3]);
                    MMAF16(acc[1][2 * g],     a1, bg[0], bg[2]);
                    MMAF16(acc[1][2 * g + 1], a1, bg[1], bg[3]);
                }
            }

            // Epilogue: fp32 direct to gmem (8-float rows = full 32B sectors)
            #pragma unroll
            for (int mi = 0; mi < 2; mi++) {
                int r = wm * 32 + mi * 16 + (lane >> 2);
                float bv0 = proj_b[r], bv1 = proj_b[r + 8];
                float* O0 = out + ((size_t)b * CCH + r) * HWSZ + sp0;
                #pragma unroll
                for (int nf = 0; nf < 4; nf++) {
                    int col = wn * 32 + nf * 8 + (lane & 3) * 2;
                    int gpos = (col >> 3) * WW + (col & 7);
                    *(float2*)(O0 + gpos) =
                        make_float2(acc[mi][nf][0] + bv0, acc[mi][nf][1] + bv0);
                    *(float2*)(O0 + (size_t)8 * HWSZ + gpos) =
                        make_float2(acc[mi][nf][2] + bv1, acc[mi][nf][3] + bv1);
                }
            }
        }
    }
}

// ---------------------------------------------------------------------------
// Launch
// ---------------------------------------------------------------------------
extern "C" void kernel_launch(void* const* d_in, const int* in_sizes, int n_in,
                              void* d_out, int out_size)
{
    const float* x      = (const float*)d_in[0];
    const float* norm_w = (const float*)d_in[1];
    const float* norm_b = (const float*)d_in[2];
    const float* qkv_w  = (const float*)d_in[3];
    const float* qkv_b  = (const float*)d_in[4];
    const float* proj_w = (const float*)d_in[5];
    const float* proj_b = (const float*)d_in[6];
    float* out = (float*)d_out;

    float *na, *nb;
    __half *wf;
    cudaGetSymbolAddress((void**)&na, g_na);
    cudaGetSymbolAddress((void**)&nb, g_nb);
    cudaGetSymbolAddress((void**)&wf, g_wf);

    int nsm = 148;
    cudaDeviceGetAttribute(&nsm, cudaDevAttrMultiProcessorCount, 0);

    cudaFuncSetAttribute(fused_kernel,
                         cudaFuncAttributeMaxDynamicSharedMemorySize, FUSED_SMEM);

    // 0) Weight convert (tiny)
    wconv_kernel<<<(4 * CCH * CCH + 255) / 256, 256>>>(qkv_w, proj_w, wf);

    // 1) LayerNorm stats
    ln_stats_kernel<<<BATCH * CCH, 256>>>(x, norm_w, norm_b, na, nb);

    // 2) Persistent fused LN-affine + QKV + attention + proj
    fused_kernel<<<nsm, 256, FUSED_SMEM>>>(
        x, wf, qkv_b, proj_b, out, na, nb);
}